// round 4
// baseline (speedup 1.0000x reference)
#include <cuda_runtime.h>

#define BB 256
#define TT 500
#define NC 100
#define NA 13

// scratch for x = FM @ lr_w^T + lr_b   [B,T,2]
__device__ float g_x[BB * TT * 2];

// ---------------------------------------------------------------------------
// Kernel 1: x[b,t,o] = sum_f FM[b,t,f] * lr_w[o,f] + lr_b[o]
// One warp per (b,t) row. Memory bound: 102.6 MB FM read.
// ---------------------------------------------------------------------------
__global__ void __launch_bounds__(256) x_kernel(const float* __restrict__ FM,
                                                const float* __restrict__ lr_w,
                                                const float* __restrict__ lr_b) {
    __shared__ float w0[200], w1[200];
    int tid = threadIdx.x;
    for (int i = tid; i < 200; i += blockDim.x) {
        w0[i] = lr_w[i];
        w1[i] = lr_w[200 + i];
    }
    __syncthreads();
    int lane = tid & 31;
    int row = blockIdx.x * (blockDim.x >> 5) + (tid >> 5);
    if (row >= BB * TT) return;
    const float* fm = FM + (size_t)row * 200;
    float a0 = 0.f, a1 = 0.f;
#pragma unroll
    for (int k = 0; k < 7; ++k) {
        int f = lane + k * 32;
        if (f < 200) {
            float v = __ldg(fm + f);
            a0 = fmaf(v, w0[f], a0);
            a1 = fmaf(v, w1[f], a1);
        }
    }
#pragma unroll
    for (int off = 16; off; off >>= 1) {
        a0 += __shfl_xor_sync(0xffffffffu, a0, off);
        a1 += __shfl_xor_sync(0xffffffffu, a1, off);
    }
    if (lane == 0) {
        g_x[row * 2 + 0] = a0 + __ldg(lr_b);
        g_x[row * 2 + 1] = a1 + __ldg(lr_b + 1);
    }
}

// ---------------------------------------------------------------------------
// Kernel 2: sequential HMM scan. One warp per batch element.
// Lane a (< 13) owns ability level a through the whole recurrence.
// ---------------------------------------------------------------------------
__device__ __forceinline__ float lse2(float a, float b) {
    float m = fmaxf(a, b);
    return m + __logf(__expf(a - m) + __expf(b - m));
}

__global__ void __launch_bounds__(32) scan_kernel(
    const int* __restrict__ corr, const int* __restrict__ kc,
    const int* __restrict__ prob, const float* __restrict__ trans_logits,
    const float* __restrict__ olp, const float* __restrict__ olk,
    const float* __restrict__ init_logits, float* __restrict__ out) {
    // smem: total 23.6 KB per block
    __shared__ float s_la[NC * 2 * NA];   // log_alpha [c][s][a]
    __shared__ float s_logt[NC * 4];      // log_softmax(trans, axis=snew) [c][snew][sold]
    __shared__ float s_olk[NC * 4];       // obs_logits_kc [c][s][o]
    __shared__ float s_x[TT * 2];         // x row for this batch
    __shared__ int s_kc[TT], s_pr[TT], s_y[TT];

    const int b = blockIdx.x;
    const int lane = threadIdx.x;

    // ---- stage per-batch rows ----
    for (int i = lane; i < TT; i += 32) {
        s_kc[i] = kc[b * TT + i];
        s_pr[i] = prob[b * TT + i];
        s_y[i]  = corr[b * TT + i];
        float2 xv = ((const float2*)g_x)[b * TT + i];
        s_x[2 * i]     = xv.x;
        s_x[2 * i + 1] = xv.y;
    }
    // ---- stage chain tables + init log_alpha ----
    for (int i = lane; i < NC; i += 32) {
        float4 v = ((const float4*)olk)[i];
        ((float4*)s_olk)[i] = v;

        float4 t = ((const float4*)trans_logits)[i];  // [snew0,sold0],[0,1],[1,0],[1,1]
        float z0 = lse2(t.x, t.z);   // normalize over snew, sold=0
        float z1 = lse2(t.y, t.w);   // sold=1
        s_logt[4 * i + 0] = t.x - z0;
        s_logt[4 * i + 1] = t.y - z1;
        s_logt[4 * i + 2] = t.z - z0;
        s_logt[4 * i + 3] = t.w - z1;

        float2 il = ((const float2*)init_logits)[i];
        float zi = lse2(il.x, il.y);
        float la00 = il.x - zi, la01 = il.y - zi;
#pragma unroll
        for (int a2 = 0; a2 < NA; ++a2) {
            s_la[i * (2 * NA) + a2]      = la00;
            s_la[i * (2 * NA) + NA + a2] = la01;
        }
    }
    __syncwarp();

    const bool act = lane < NA;
    const int a = act ? lane : (NA - 1);
    const float abv = -3.0f + 0.5f * (float)a;   // ab[a]; abilities[0][a]=-abv, [1][a]=+abv
    float ability = -2.5649493574615367f;        // -log(13)

    const float4* olp4 = (const float4*)olp;
    float4 olp_cur = __ldg(olp4 + s_pr[0]);      // prefetch step 0

    for (int t = 0; t < TT; ++t) {
        float4 op = olp_cur;
        if (t + 1 < TT) olp_cur = __ldg(olp4 + s_pr[t + 1]);  // prefetch next step

        const int c = s_kc[t];
        const int y = s_y[t];
        const float x0 = s_x[2 * t], x1 = s_x[2 * t + 1];
        const float4 ok = ((const float4*)s_olk)[c];

        // logit[s][o] = olp[p][s][o] + olk[c][s][o] + abilities[o][a] + olfv[s][o]
        float l00 = op.x + ok.x - abv + x0;
        float l01 = op.y + ok.y + abv - x0;
        float l10 = op.z + ok.z - abv + x1;
        float l11 = op.w + ok.w + abv - x1;
        // log_obs = log_softmax over o (per s)
        float z0 = lse2(l00, l01);
        float z1 = lse2(l10, l11);
        float lo00 = l00 - z0, lo01 = l01 - z0;
        float lo10 = l10 - z1, lo11 = l11 - z1;

        // log_alpha slice (read pre-update; cell [c,s,a] only ever touched by lane a)
        float la0v = s_la[c * (2 * NA) + a];
        float la1v = s_la[c * (2 * NA) + NA + a];

        // log_py_given_beta[o] = lse_s(log_obs[s][o] + la[s]), normalized over o
        float g0 = lse2(lo00 + la0v, lo10 + la1v);
        float g1 = lse2(lo01 + la0v, lo11 + la1v);
        float zn = lse2(g0, g1);
        g0 -= zn;
        g1 -= zn;

        // new_la[snew] = lse_sold(log_obs[sold][y] + la[sold] + log_t[c][snew][sold])
        float lps0 = (y == 0) ? lo00 : lo01;
        float lps1 = (y == 0) ? lo10 : lo11;
        float q0 = lps0 + la0v;
        float q1 = lps1 + la1v;
        float nla0 = lse2(q0 + s_logt[4 * c + 0], q1 + s_logt[4 * c + 1]);
        float nla1 = lse2(q0 + s_logt[4 * c + 2], q1 + s_logt[4 * c + 3]);
        if (act) {
            s_la[c * (2 * NA) + a]      = nla0;
            s_la[c * (2 * NA) + NA + a] = nla1;
        }

        // out[o] = lse_a(ability_pre + g[o]) ; normalized over o  (off the recurrence)
        float v0 = act ? (ability + g0) : -1e30f;
        float v1 = act ? (ability + g1) : -1e30f;
        float M0 = v0, M1 = v1;
#pragma unroll
        for (int off = 8; off; off >>= 1) {  // reduce within 16-lane half (13 active)
            M0 = fmaxf(M0, __shfl_xor_sync(0xffffffffu, M0, off));
            M1 = fmaxf(M1, __shfl_xor_sync(0xffffffffu, M1, off));
        }
        float e0 = __expf(v0 - M0), e1 = __expf(v1 - M1);
#pragma unroll
        for (int off = 8; off; off >>= 1) {
            e0 += __shfl_xor_sync(0xffffffffu, e0, off);
            e1 += __shfl_xor_sync(0xffffffffu, e1, off);
        }

        // ability update uses pre-update value only in out above
        ability += (y == 0) ? g0 : g1;

        if (lane == 0) {
            float o0 = M0 + __logf(e0);
            float o1 = M1 + __logf(e1);
            float zo = lse2(o0, o1);
            ((float2*)out)[b * TT + t] = make_float2(o0 - zo, o1 - zo);
        }
    }
}

// ---------------------------------------------------------------------------
// Harness entry
// inputs: 0 corr[i32 B,T] 1 kc[i32] 2 problem[i32] 3 FM[f32 B,T,200]
//         4 trans_logits[f32 100,2,2] 5 obs_logits_problem[f32 10000,2,2]
//         6 obs_logits_kc[f32 100,2,2] 7 init_logits[f32 100,2]
//         8 lr_w[f32 2,200] 9 lr_b[f32 2]     output: f32 [B,T,2]
// ---------------------------------------------------------------------------
extern "C" void kernel_launch(void* const* d_in, const int* in_sizes, int n_in,
                              void* d_out, int out_size) {
    const int*   corr = (const int*)d_in[0];
    const int*   kcp  = (const int*)d_in[1];
    const int*   prob = (const int*)d_in[2];
    const float* FM   = (const float*)d_in[3];
    const float* tl   = (const float*)d_in[4];
    const float* olp  = (const float*)d_in[5];
    const float* olk  = (const float*)d_in[6];
    const float* il   = (const float*)d_in[7];
    const float* lrw  = (const float*)d_in[8];
    const float* lrb  = (const float*)d_in[9];
    float* out = (float*)d_out;

    // 8 warps per block, 1 row per warp
    x_kernel<<<(BB * TT + 7) / 8, 256>>>(FM, lrw, lrb);
    scan_kernel<<<BB, 32>>>(corr, kcp, prob, tl, olp, olk, il, out);
}

// round 5
// speedup vs baseline: 2.7202x; 2.7202x over previous
#include <cuda_runtime.h>

#define BB 256
#define TT 500
#define NC 100
#define NA 13

// scratch: x = FM @ lr_w^T + lr_b  [B,T,2]
__device__ float g_x[BB * TT * 2];
// scratch: per-(b,t,a) pre-reduction output values (ability_pre + gN)
__device__ float2 g_v[BB * TT * NA];

// ---------------------------------------------------------------------------
// Kernel 1: x[b,t,o] = sum_f FM[b,t,f] * lr_w[o,f] + lr_b[o]
// One warp per (b,t) row, float4 loads. Memory bound (102.6 MB FM).
// ---------------------------------------------------------------------------
__global__ void __launch_bounds__(256) x_kernel(const float* __restrict__ FM,
                                                const float* __restrict__ lr_w,
                                                const float* __restrict__ lr_b) {
    __shared__ float4 w0[50], w1[50];
    int tid = threadIdx.x;
    if (tid < 50) {
        w0[tid] = ((const float4*)lr_w)[tid];
        w1[tid] = ((const float4*)lr_w)[50 + tid];
    }
    __syncthreads();
    int lane = tid & 31;
    int row = blockIdx.x * 8 + (tid >> 5);
    if (row >= BB * TT) return;
    const float4* fm4 = (const float4*)(FM + (size_t)row * 200);
    float a0 = 0.f, a1 = 0.f;
    {
        float4 v = __ldg(fm4 + lane);
        float4 u = w0[lane], s = w1[lane];
        a0 = v.x * u.x + v.y * u.y + v.z * u.z + v.w * u.w;
        a1 = v.x * s.x + v.y * s.y + v.z * s.z + v.w * s.w;
    }
    if (lane < 18) {
        float4 v = __ldg(fm4 + lane + 32);
        float4 u = w0[lane + 32], s = w1[lane + 32];
        a0 += v.x * u.x + v.y * u.y + v.z * u.z + v.w * u.w;
        a1 += v.x * s.x + v.y * s.y + v.z * s.z + v.w * s.w;
    }
#pragma unroll
    for (int off = 16; off; off >>= 1) {
        a0 += __shfl_xor_sync(0xffffffffu, a0, off);
        a1 += __shfl_xor_sync(0xffffffffu, a1, off);
    }
    if (lane == 0) {
        ((float2*)g_x)[row] = make_float2(a0 + __ldg(lr_b), a1 + __ldg(lr_b + 1));
    }
}

// ---------------------------------------------------------------------------
// Kernel 2: sequential HMM scan, exp-space math. One warp per batch element.
// Lane a (< 13) owns ability level a. Output reduction deferred to kernel 3.
// ---------------------------------------------------------------------------
__global__ void __launch_bounds__(32) scan_kernel(
    const int* __restrict__ corr, const int* __restrict__ kc,
    const int* __restrict__ prob, const float* __restrict__ trans_logits,
    const float* __restrict__ olp, const float* __restrict__ olk,
    const float* __restrict__ init_logits) {
    __shared__ float  s_la[NC * 2 * NA];  // log_alpha [c][s][a]
    __shared__ float4 s_T[TT + 1];        // per-step trans probs (T00,T01,T10,T11)
    __shared__ float2 s_D[TT + 1];        // per-step D base (dop+dok-2x) per s
    __shared__ int    s_kc[TT + 1];
    __shared__ int    s_y[TT + 1];

    const int b = blockIdx.x;
    const int lane = threadIdx.x;
    const int laneA = (lane < NA) ? lane : 0;

    const float4* olp4 = (const float4*)olp;
    const float4* olk4 = (const float4*)olk;
    const float4* tl4  = (const float4*)trans_logits;
    const float2* gx2  = (const float2*)g_x;

    // ---- stage per-step tables ----
    for (int i = lane; i < TT; i += 32) {
        int c = kc[b * TT + i];
        int p = prob[b * TT + i];
        s_kc[i] = c;
        s_y[i]  = corr[b * TT + i];
        float4 op = __ldg(olp4 + p);
        float4 ok = __ldg(olk4 + c);
        float2 xv = gx2[b * TT + i];
        s_D[i] = make_float2((op.y - op.x) + (ok.y - ok.x) - 2.f * xv.x,
                             (op.w - op.z) + (ok.w - ok.z) - 2.f * xv.y);
        // trans probs: softmax over snew (pairs (x,z) and (y,w))
        float4 t = __ldg(tl4 + c);
        float m0 = fmaxf(t.x, t.z), m1 = fmaxf(t.y, t.w);
        float e00 = __expf(t.x - m0), e10 = __expf(t.z - m0);
        float e01 = __expf(t.y - m1), e11 = __expf(t.w - m1);
        float r0 = __fdividef(1.f, e00 + e10);
        float r1 = __fdividef(1.f, e01 + e11);
        s_T[i] = make_float4(e00 * r0, e01 * r1, e10 * r0, e11 * r1);
    }
    if (lane == 0) {
        s_kc[TT] = 0; s_y[TT] = 0;
        s_D[TT] = make_float2(0.f, 0.f);
        s_T[TT] = make_float4(0.5f, 0.5f, 0.5f, 0.5f);
    }
    // ---- init log_alpha ----
    for (int i = lane; i < NC; i += 32) {
        float2 il = ((const float2*)init_logits)[i];
        float m = fmaxf(il.x, il.y);
        float z = m + __logf(__expf(il.x - m) + __expf(il.y - m));
        float la00 = il.x - z, la01 = il.y - z;
#pragma unroll
        for (int a2 = 0; a2 < NA; ++a2) {
            s_la[i * (2 * NA) + a2]      = la00;
            s_la[i * (2 * NA) + NA + a2] = la01;
        }
    }
    __syncwarp();

    const bool act = lane < NA;
    const float ab2 = 2.f * (-3.0f + 0.5f * (float)laneA);  // 2*ab[a]
    float ability = -2.5649493574615367f;                   // -log(13)
    float2* gv = g_v + (size_t)b * TT * NA + lane;

    int c = s_kc[0];
    int y = s_y[0];
    float2 D  = s_D[0];
    float4 T  = s_T[0];
    float la0 = s_la[c * (2 * NA) + laneA];
    float la1 = s_la[c * (2 * NA) + NA + laneA];

#pragma unroll 2
    for (int t = 0; t < TT; ++t) {
        // ---- prefetch t+1 (la read BEFORE this step's store; same-chain forwarded) ----
        int   c1   = s_kc[t + 1];
        int   y1   = s_y[t + 1];
        float2 Dn  = s_D[t + 1];
        float4 Tn  = s_T[t + 1];
        float la0n = s_la[c1 * (2 * NA) + laneA];
        float la1n = s_la[c1 * (2 * NA) + NA + laneA];

        // ---- obs probs: p_so = softmax over o = sigmoid of logit diff ----
        float D0 = D.x + ab2, D1 = D.y + ab2;
        float e0 = __expf(-fabsf(D0));
        float r0 = __fdividef(1.f, 1.f + e0);
        float pm0 = e0 * r0;
        float p00 = (D0 >= 0.f) ? pm0 : r0;
        float p01 = (D0 >= 0.f) ? r0 : pm0;
        float e1 = __expf(-fabsf(D1));
        float r1 = __fdividef(1.f, 1.f + e1);
        float pm1 = e1 * r1;
        float p10 = (D1 >= 0.f) ? pm1 : r1;
        float p11 = (D1 >= 0.f) ? r1 : pm1;

        // ---- alpha weights ----
        float mla = fmaxf(la0, la1);
        float A0 = __expf(la0 - mla), A1 = __expf(la1 - mla);
        float P00 = p00 * A0, P10 = p10 * A1;
        float P01 = p01 * A0, P11 = p11 * A1;
        float G0 = P00 + P10, G1 = P01 + P11;
        float lg0 = __logf(G0), lg1 = __logf(G1);
        float ls  = __logf(G0 + G1);
        float gN0 = lg0 - ls, gN1 = lg1 - ls;  // normalized log_py_given_beta

        // ---- output values (pre-ability-update), reduced in kernel 3 ----
        if (act) gv[t * NA] = make_float2(ability + gN0, ability + gN1);
        ability += y ? gN1 : gN0;

        // ---- alpha update: nla = mla + log(sum_sold p_sy*A_s * T[snew][sold]) ----
        float u0 = y ? P01 : P00;
        float u1 = y ? P11 : P10;
        float nla0 = mla + __logf(u0 * T.x + u1 * T.y);
        float nla1 = mla + __logf(u0 * T.z + u1 * T.w);
        if (act) {
            s_la[c * (2 * NA) + lane]      = nla0;
            s_la[c * (2 * NA) + NA + lane] = nla1;
        }

        // ---- rotate; forward registers if next step hits the same chain ----
        bool same = (c1 == c);
        la0 = same ? nla0 : la0n;
        la1 = same ? nla1 : la1n;
        c = c1; y = y1; D = Dn; T = Tn;
    }
}

// ---------------------------------------------------------------------------
// Kernel 3: out[b,t,o] = normalize_o( lse_a( v[b,t,a,o] ) ). One warp per row.
// ---------------------------------------------------------------------------
__global__ void __launch_bounds__(256) out_kernel(float* __restrict__ out) {
    int row = blockIdx.x * 8 + (threadIdx.x >> 5);
    int lane = threadIdx.x & 31;
    if (row >= BB * TT) return;
    float v0 = -1e30f, v1 = -1e30f;
    if (lane < NA) {
        float2 v = g_v[(size_t)row * NA + lane];
        v0 = v.x; v1 = v.y;
    }
    float M0 = v0, M1 = v1;
#pragma unroll
    for (int off = 8; off; off >>= 1) {
        M0 = fmaxf(M0, __shfl_xor_sync(0xffffffffu, M0, off));
        M1 = fmaxf(M1, __shfl_xor_sync(0xffffffffu, M1, off));
    }
    float e0 = __expf(v0 - M0), e1 = __expf(v1 - M1);
#pragma unroll
    for (int off = 8; off; off >>= 1) {
        e0 += __shfl_xor_sync(0xffffffffu, e0, off);
        e1 += __shfl_xor_sync(0xffffffffu, e1, off);
    }
    if (lane == 0) {
        float o0 = M0 + __logf(e0);
        float o1 = M1 + __logf(e1);
        float m = fmaxf(o0, o1);
        float zo = m + __logf(__expf(o0 - m) + __expf(o1 - m));
        ((float2*)out)[row] = make_float2(o0 - zo, o1 - zo);
    }
}

// ---------------------------------------------------------------------------
// inputs: 0 corr[i32 B,T] 1 kc 2 problem 3 FM[f32 B,T,200]
//         4 trans_logits[f32 100,2,2] 5 obs_logits_problem[f32 10000,2,2]
//         6 obs_logits_kc[f32 100,2,2] 7 init_logits[f32 100,2]
//         8 lr_w[f32 2,200] 9 lr_b[f32 2]     output: f32 [B,T,2]
// ---------------------------------------------------------------------------
extern "C" void kernel_launch(void* const* d_in, const int* in_sizes, int n_in,
                              void* d_out, int out_size) {
    const int*   corr = (const int*)d_in[0];
    const int*   kcp  = (const int*)d_in[1];
    const int*   prob = (const int*)d_in[2];
    const float* FM   = (const float*)d_in[3];
    const float* tl   = (const float*)d_in[4];
    const float* olp  = (const float*)d_in[5];
    const float* olk  = (const float*)d_in[6];
    const float* il   = (const float*)d_in[7];
    const float* lrw  = (const float*)d_in[8];
    const float* lrb  = (const float*)d_in[9];
    float* out = (float*)d_out;

    x_kernel<<<(BB * TT + 7) / 8, 256>>>(FM, lrw, lrb);
    scan_kernel<<<BB, 32>>>(corr, kcp, prob, tl, olp, olk, il);
    out_kernel<<<(BB * TT + 7) / 8, 256>>>(out);
}

// round 6
// speedup vs baseline: 3.0067x; 1.1053x over previous
#include <cuda_runtime.h>

#define BB 256
#define TT 500
#define NC 100
#define NA 13

// scratch: x = FM @ lr_w^T + lr_b  [B,T,2]
__device__ float g_x[BB * TT * 2];
// scratch: per-(b,t,a) pre-reduction output values (ability_pre + gN)
__device__ float2 g_v[BB * TT * NA];

// ---------------------------------------------------------------------------
// Kernel 1: x[b,t,o] = sum_f FM[b,t,f] * lr_w[o,f] + lr_b[o]
// Two rows per warp (4 in-flight LDG.128), float4 output store.
// ---------------------------------------------------------------------------
__global__ void __launch_bounds__(256) x_kernel(const float* __restrict__ FM,
                                                const float* __restrict__ lr_w,
                                                const float* __restrict__ lr_b) {
    __shared__ float4 w0[50], w1[50];
    int tid = threadIdx.x;
    if (tid < 50) {
        w0[tid] = ((const float4*)lr_w)[tid];
        w1[tid] = ((const float4*)lr_w)[50 + tid];
    }
    __syncthreads();
    int lane = tid & 31;
    int wrow = (blockIdx.x * 8 + (tid >> 5)) * 2;  // rows wrow, wrow+1
    if (wrow >= BB * TT) return;
    const float4* fa = (const float4*)(FM + (size_t)wrow * 200);
    const float4* fb = fa + 50;

    float4 va0 = __ldg(fa + lane);
    float4 vb0 = __ldg(fb + lane);
    float4 va1, vb1;
    bool tail = lane < 18;
    if (tail) {
        va1 = __ldg(fa + 32 + lane);
        vb1 = __ldg(fb + 32 + lane);
    }
    float4 u = w0[lane], s = w1[lane];
    float a0 = va0.x * u.x + va0.y * u.y + va0.z * u.z + va0.w * u.w;
    float a1 = va0.x * s.x + va0.y * s.y + va0.z * s.z + va0.w * s.w;
    float b0 = vb0.x * u.x + vb0.y * u.y + vb0.z * u.z + vb0.w * u.w;
    float b1 = vb0.x * s.x + vb0.y * s.y + vb0.z * s.z + vb0.w * s.w;
    if (tail) {
        float4 u2 = w0[32 + lane], s2 = w1[32 + lane];
        a0 += va1.x * u2.x + va1.y * u2.y + va1.z * u2.z + va1.w * u2.w;
        a1 += va1.x * s2.x + va1.y * s2.y + va1.z * s2.z + va1.w * s2.w;
        b0 += vb1.x * u2.x + vb1.y * u2.y + vb1.z * u2.z + vb1.w * u2.w;
        b1 += vb1.x * s2.x + vb1.y * s2.y + vb1.z * s2.z + vb1.w * s2.w;
    }
#pragma unroll
    for (int off = 16; off; off >>= 1) {
        a0 += __shfl_xor_sync(0xffffffffu, a0, off);
        a1 += __shfl_xor_sync(0xffffffffu, a1, off);
        b0 += __shfl_xor_sync(0xffffffffu, b0, off);
        b1 += __shfl_xor_sync(0xffffffffu, b1, off);
    }
    if (lane == 0) {
        float bb0 = __ldg(lr_b), bb1 = __ldg(lr_b + 1);
        ((float4*)g_x)[wrow >> 1] = make_float4(a0 + bb0, a1 + bb1, b0 + bb0, b1 + bb1);
    }
}

// ---------------------------------------------------------------------------
// Kernel 2: sequential scan with LINEAR-space alpha (normalized to sum 1).
// One warp per batch; lane a (< 13) owns ability level a.
//   p_so precomputable from D[t]; G0+G1 = 1; nA0+nA1 = G_y;
//   recurrence chain: mul -> sel -> fma -> mul (+ one fdividef, overlapped).
// ---------------------------------------------------------------------------
__global__ void __launch_bounds__(32) scan_kernel(
    const int* __restrict__ corr, const int* __restrict__ kc,
    const int* __restrict__ prob, const float* __restrict__ trans_logits,
    const float* __restrict__ olp, const float* __restrict__ olk,
    const float* __restrict__ init_logits) {
    __shared__ float  s_la[NC * 2 * NA];  // linear alpha [c][s][a], sum_s = 1
    __shared__ float4 s_T[TT + 1];        // per-step trans probs (T00,T01,T10,T11)
    __shared__ float2 s_D[TT + 1];        // per-step logit-diff base per s
    __shared__ int    s_kc[TT + 1];
    __shared__ int    s_y[TT + 1];

    const int b = blockIdx.x;
    const int lane = threadIdx.x;
    const int laneA = (lane < NA) ? lane : 0;

    const float4* olp4 = (const float4*)olp;
    const float4* olk4 = (const float4*)olk;
    const float4* tl4  = (const float4*)trans_logits;
    const float2* gx2  = (const float2*)g_x;

    // ---- stage per-step tables ----
    for (int i = lane; i < TT; i += 32) {
        int c = kc[b * TT + i];
        int p = prob[b * TT + i];
        s_kc[i] = c;
        s_y[i]  = corr[b * TT + i];
        float4 op = __ldg(olp4 + p);
        float4 ok = __ldg(olk4 + c);
        float2 xv = gx2[b * TT + i];
        s_D[i] = make_float2((op.y - op.x) + (ok.y - ok.x) - 2.f * xv.x,
                             (op.w - op.z) + (ok.w - ok.z) - 2.f * xv.y);
        // trans probs: softmax over snew (pairs (x,z) and (y,w))
        float4 t = __ldg(tl4 + c);
        float m0 = fmaxf(t.x, t.z), m1 = fmaxf(t.y, t.w);
        float e00 = __expf(t.x - m0), e10 = __expf(t.z - m0);
        float e01 = __expf(t.y - m1), e11 = __expf(t.w - m1);
        float r0 = __fdividef(1.f, e00 + e10);
        float r1 = __fdividef(1.f, e01 + e11);
        s_T[i] = make_float4(e00 * r0, e01 * r1, e10 * r0, e11 * r1);
    }
    if (lane == 0) {
        s_kc[TT] = 0; s_y[TT] = 0;
        s_D[TT] = make_float2(0.f, 0.f);
        s_T[TT] = make_float4(0.5f, 0.5f, 0.5f, 0.5f);
    }
    // ---- init alpha (linear, normalized) ----
    for (int i = lane; i < NC; i += 32) {
        float2 il = ((const float2*)init_logits)[i];
        float m = fmaxf(il.x, il.y);
        float ex = __expf(il.x - m), ey = __expf(il.y - m);
        float r = __fdividef(1.f, ex + ey);
        float A0i = ex * r, A1i = ey * r;
#pragma unroll
        for (int a2 = 0; a2 < NA; ++a2) {
            s_la[i * (2 * NA) + a2]      = A0i;
            s_la[i * (2 * NA) + NA + a2] = A1i;
        }
    }
    __syncwarp();

    const bool act = lane < NA;
    const float ab2 = 2.f * (-3.0f + 0.5f * (float)laneA);  // 2*ab[a]
    float ability = -2.5649493574615367f;                   // -log(13)
    float2* gv = g_v + (size_t)b * TT * NA + lane;

    int c = s_kc[0];
    int y = s_y[0];
    float2 D  = s_D[0];
    float4 T  = s_T[0];
    float A0 = s_la[c * (2 * NA) + laneA];
    float A1 = s_la[c * (2 * NA) + NA + laneA];

#pragma unroll 4
    for (int t = 0; t < TT; ++t) {
        // ---- prefetch t+1 (alpha read BEFORE this step's store; same-chain forwarded) ----
        int    c1  = s_kc[t + 1];
        int    y1  = s_y[t + 1];
        float2 Dn  = s_D[t + 1];
        float4 Tn  = s_T[t + 1];
        float  A0n = s_la[c1 * (2 * NA) + laneA];
        float  A1n = s_la[c1 * (2 * NA) + NA + laneA];

        // ---- obs probs p_so (independent of recurrence) ----
        float D0 = D.x + ab2, D1 = D.y + ab2;
        float e0 = __expf(-fabsf(D0));
        float r0 = __fdividef(1.f, 1.f + e0);
        float pm0 = e0 * r0;
        float p00 = (D0 >= 0.f) ? pm0 : r0;
        float p01 = (D0 >= 0.f) ? r0 : pm0;
        float e1 = __expf(-fabsf(D1));
        float r1 = __fdividef(1.f, 1.f + e1);
        float pm1 = e1 * r1;
        float p10 = (D1 >= 0.f) ? pm1 : r1;
        float p11 = (D1 >= 0.f) ? r1 : pm1;

        // ---- joint probs; G0+G1 = 1 by construction ----
        float P00 = p00 * A0, P10 = p10 * A1;
        float P01 = p01 * A0, P11 = p11 * A1;
        float G0 = P00 + P10, G1 = P01 + P11;

        // ---- output side chain (logs only feed ability/output) ----
        float lg0 = __logf(G0), lg1 = __logf(G1);
        if (act) gv[t * NA] = make_float2(ability + lg0, ability + lg1);
        ability += y ? lg1 : lg0;

        // ---- alpha update: nA = T @ u, renormalized by Gy = nA0+nA1 ----
        float u0 = y ? P01 : P00;
        float u1 = y ? P11 : P10;
        float Gy = y ? G1 : G0;
        float nA0 = fmaf(u0, T.x, u1 * T.y);
        float nA1 = fmaf(u0, T.z, u1 * T.w);
        float rcp = __fdividef(1.f, Gy);
        float A0p = nA0 * rcp;
        float A1p = nA1 * rcp;
        if (act) {
            s_la[c * (2 * NA) + lane]      = A0p;
            s_la[c * (2 * NA) + NA + lane] = A1p;
        }

        // ---- rotate; forward registers if next step hits the same chain ----
        bool same = (c1 == c);
        A0 = same ? A0p : A0n;
        A1 = same ? A1p : A1n;
        c = c1; y = y1; D = Dn; T = Tn;
    }
}

// ---------------------------------------------------------------------------
// Kernel 3: out[b,t,o] = normalize_o( lse_a( v[b,t,a,o] ) ). One warp per row.
// ---------------------------------------------------------------------------
__global__ void __launch_bounds__(256) out_kernel(float* __restrict__ out) {
    int row = blockIdx.x * 8 + (threadIdx.x >> 5);
    int lane = threadIdx.x & 31;
    if (row >= BB * TT) return;
    float v0 = -1e30f, v1 = -1e30f;
    if (lane < NA) {
        float2 v = g_v[(size_t)row * NA + lane];
        v0 = v.x; v1 = v.y;
    }
    float M0 = v0, M1 = v1;
#pragma unroll
    for (int off = 8; off; off >>= 1) {
        M0 = fmaxf(M0, __shfl_xor_sync(0xffffffffu, M0, off));
        M1 = fmaxf(M1, __shfl_xor_sync(0xffffffffu, M1, off));
    }
    float e0 = __expf(v0 - M0), e1 = __expf(v1 - M1);
#pragma unroll
    for (int off = 8; off; off >>= 1) {
        e0 += __shfl_xor_sync(0xffffffffu, e0, off);
        e1 += __shfl_xor_sync(0xffffffffu, e1, off);
    }
    if (lane == 0) {
        float o0 = M0 + __logf(e0);
        float o1 = M1 + __logf(e1);
        float m = fmaxf(o0, o1);
        float zo = m + __logf(__expf(o0 - m) + __expf(o1 - m));
        ((float2*)out)[row] = make_float2(o0 - zo, o1 - zo);
    }
}

// ---------------------------------------------------------------------------
// inputs: 0 corr[i32 B,T] 1 kc 2 problem 3 FM[f32 B,T,200]
//         4 trans_logits[f32 100,2,2] 5 obs_logits_problem[f32 10000,2,2]
//         6 obs_logits_kc[f32 100,2,2] 7 init_logits[f32 100,2]
//         8 lr_w[f32 2,200] 9 lr_b[f32 2]     output: f32 [B,T,2]
// ---------------------------------------------------------------------------
extern "C" void kernel_launch(void* const* d_in, const int* in_sizes, int n_in,
                              void* d_out, int out_size) {
    const int*   corr = (const int*)d_in[0];
    const int*   kcp  = (const int*)d_in[1];
    const int*   prob = (const int*)d_in[2];
    const float* FM   = (const float*)d_in[3];
    const float* tl   = (const float*)d_in[4];
    const float* olp  = (const float*)d_in[5];
    const float* olk  = (const float*)d_in[6];
    const float* il   = (const float*)d_in[7];
    const float* lrw  = (const float*)d_in[8];
    const float* lrb  = (const float*)d_in[9];
    float* out = (float*)d_out;

    x_kernel<<<(BB * TT / 2 + 7) / 8, 256>>>(FM, lrw, lrb);
    scan_kernel<<<BB, 32>>>(corr, kcp, prob, tl, olp, olk, il);
    out_kernel<<<(BB * TT + 7) / 8, 256>>>(out);
}